// round 7
// baseline (speedup 1.0000x reference)
#include <cuda_runtime.h>
#include <cuda_fp16.h>
#include <cstdint>
#include <math.h>

// Problem constants
#define BTOT 128
#define HDIM 128
#define ADIM 384
#define MT   128            // edges per CTA tile
#define NTHREADS 256        // 8 warps
#define NCHUNKS 36          // 3 n-chunks x 12 k-chunks (k=32 each)

#define A_STRH 40           // A chunk [128][32] halves, padded stride (conflict-free frags)
#define W_STRH 40           // W chunk [128 n][32 k] halves, padded stride
#define A_CH (MT * A_STRH)       // 5120 halves per buffer
#define W_CH (128 * W_STRH)      // 5120 halves per buffer

// SMEM bytes: A 2 bufs + W 3 bufs + b1 + score + eb  = 53760 B -> 2 CTAs/SM (regs-bound)
#define SMEM_BYTES (2 * A_CH * 2 + 3 * W_CH * 2 + ADIM * 4 + MT * 4 + MT * 4)

// device scratch (no cudaMalloc allowed)
__device__ float g_query[BTOT * ADIM];
__device__ float g_qT[ADIM * BTOT];
__device__ float g_z[BTOT * ADIM];
__device__ float g_cb[BTOT];
__device__ __align__(16) __half g_CT[ADIM * ADIM];  // fused weight fp16, [n][k] layout

__device__ __forceinline__ float gelu_exact(float x) {
    return 0.5f * x * (1.0f + erff(x * 0.7071067811865476f));
}

// mma.sync m16n8k16 fp16: D(f32) += A(16x16 f16, row) * B(16x8 f16, col)
__device__ __forceinline__ void mma_f16(float* c, const unsigned* a, const unsigned* b) {
    asm volatile(
        "mma.sync.aligned.m16n8k16.row.col.f32.f16.f16.f32 "
        "{%0,%1,%2,%3}, {%4,%5,%6,%7}, {%8,%9}, {%0,%1,%2,%3};"
        : "+f"(c[0]), "+f"(c[1]), "+f"(c[2]), "+f"(c[3])
        : "r"(a[0]), "r"(a[1]), "r"(a[2]), "r"(a[3]), "r"(b[0]), "r"(b[1]));
}

__device__ __forceinline__ void cp16(uint32_t smem_dst, const void* gsrc) {
    asm volatile("cp.async.cg.shared.global [%0], [%1], 16;"
                 :: "r"(smem_dst), "l"(__cvta_generic_to_global(gsrc)) : "memory");
}
__device__ __forceinline__ void cp_commit() {
    asm volatile("cp.async.commit_group;" ::: "memory");
}
template <int N>
__device__ __forceinline__ void cp_wait() {
    asm volatile("cp.async.wait_group %0;" :: "n"(N) : "memory");
}
__device__ __forceinline__ uint32_t smem_u32(const void* p) {
    uint32_t a;
    asm("{ .reg .u64 t; cvta.to.shared.u64 t, %1; cvt.u32.u64 %0, t; }" : "=r"(a) : "l"(p));
    return a;
}
__device__ __forceinline__ uint32_t pk_h2(float a, float b) {
    __half2 t = __floats2half2_rn(a, b);   // a -> low half
    return *(uint32_t*)&t;
}

// ---------------------------------------------------------------------------
// Prep kernels (exact fp32 math, validated since R3)
// ---------------------------------------------------------------------------
__global__ void query_kernel(const float* __restrict__ hidden, const float* __restrict__ Wq) {
    __shared__ float hrow[HDIM];
    const int b = blockIdx.x, a = threadIdx.x;
    if (a < HDIM) hrow[a] = hidden[b * HDIM + a];
    __syncthreads();
    float s = 0.f;
    #pragma unroll 8
    for (int h = 0; h < HDIM; h++) s += hrow[h] * Wq[h * ADIM + a];
    g_query[b * ADIM + a] = s;
    g_qT[a * BTOT + b] = s;
}

__global__ void z_kernel(const float* __restrict__ W2) {
    __shared__ float wrow[ADIM];
    const int k = blockIdx.x, b = threadIdx.x;
    for (int i = b; i < ADIM; i += 128) wrow[i] = W2[k * ADIM + i];
    __syncthreads();
    float s = 0.f;
    #pragma unroll 8
    for (int n = 0; n < ADIM; n++) s += wrow[n] * g_qT[n * BTOT + b];
    g_z[b * ADIM + k] = s;
}

__global__ void cb_kernel(const float* __restrict__ b2) {
    __shared__ float red[12];
    const int b = blockIdx.x, t = threadIdx.x;
    float v = b2[t] * g_query[b * ADIM + t];
    #pragma unroll
    for (int o = 16; o > 0; o >>= 1) v += __shfl_down_sync(0xffffffffu, v, o);
    if ((t & 31) == 0) red[t >> 5] = v;
    __syncthreads();
    if (t == 0) {
        float s = 0.f;
        #pragma unroll
        for (int i = 0; i < 12; i++) s += red[i];
        g_cb[b] = s;
    }
}

// C = blockdiag(Wr,Wn,Wh) @ W1, exact fp32, stored fp16 TRANSPOSED [n][k]
__global__ void c_kernel(const float* __restrict__ Wr, const float* __restrict__ Wn,
                         const float* __restrict__ Wh, const float* __restrict__ W1) {
    __shared__ float wrow[HDIM];
    const int kg = blockIdx.x, n = threadIdx.x;
    const int t = kg >> 7, d = kg & 127;
    const float* Wt = (t == 0) ? Wr : ((t == 1) ? Wn : Wh);
    if (n < HDIM) wrow[n] = Wt[d * HDIM + n];
    __syncthreads();
    float s = 0.f;
    #pragma unroll 8
    for (int h = 0; h < HDIM; h++) s += wrow[h] * W1[(t * HDIM + h) * ADIM + n];
    g_CT[n * ADIM + kg] = __float2half_rn(s);
}

// ---------------------------------------------------------------------------
// Main fused kernel: G = X @ C via fp16 m16n8k16; scores = gelu(G+b1).z[eb]+cb[eb]
// 8 warps in 2x4 over [128 x 128]; warp tile 64x32 (4m x 4n). acc 64 regs.
// A: register-lookahead LDG fp32 -> cvt fp16 -> STS (double buffer).
// W: fp16 cp.async 3-stage from transposed g_CT.
// ---------------------------------------------------------------------------
__global__ void __launch_bounds__(NTHREADS, 2)
fused_kernel(const float* __restrict__ rel, const float* __restrict__ nod,
             const float* __restrict__ hed, const int* __restrict__ edge_batch,
             const float* __restrict__ b1, float* __restrict__ out)
{
    extern __shared__ char smem[];
    __half* Asm    = (__half*)smem;                       // 2 * A_CH
    __half* Wsm    = Asm + 2 * A_CH;                      // 3 * W_CH
    float*  b1s    = (float*)(Wsm + 3 * W_CH);
    float*  score_s = b1s + ADIM;
    int*    eb_s   = (int*)(score_s + MT);

    const int tid   = threadIdx.x;
    const int lane  = tid & 31;
    const int warp  = tid >> 5;
    const int group = lane >> 2;
    const int t4    = lane & 3;
    const int m_off = (warp >> 2) * 64;   // 0 or 64
    const int n_off = (warp & 3) * 32;    // 0..96
    const long e0   = (long)blockIdx.x * MT;

    if (tid < MT) {
        eb_s[tid] = edge_batch[e0 + tid];
        score_s[tid] = 0.f;
    }
    for (int i = tid; i < ADIM; i += NTHREADS) b1s[i] = b1[i];

    const uint32_t sW = smem_u32(Wsm);

    // W chunk m -> buffer m%3 : 128 n-rows x 32 k halves, 2 cp16/thread
    auto issue_W = [&](int m) {
        const int nc = m / 12;
        const int k0 = (m - nc * 12) * 32;
        const uint32_t base = sW + (m % 3) * (W_CH * 2);
        #pragma unroll
        for (int j = 0; j < 2; j++) {
            const int idx = tid + NTHREADS * j;
            const int n = idx >> 2, c = idx & 3;
            cp16(base + (n * W_STRH + c * 8) * 2,
                 g_CT + (long)(nc * 128 + n) * ADIM + k0 + c * 8);
        }
        cp_commit();
    };

    // A chunk lookahead: 16 floats/thread (row = tid>>1, half = (tid&1)*16 cols)
    const int arow = tid >> 1, acol = (tid & 1) * 16;
    float4 aReg[4];
    auto ldg_A = [&](int m) {
        const int nc = m / 12;
        const int k0 = (m - nc * 12) * 32;
        const int tt = k0 >> 7, col0 = k0 & 127;
        const float* src = (tt == 0) ? rel : ((tt == 1) ? nod : hed);
        const float* p = src + (e0 + arow) * HDIM + col0 + acol;
        aReg[0] = *(const float4*)(p);
        aReg[1] = *(const float4*)(p + 4);
        aReg[2] = *(const float4*)(p + 8);
        aReg[3] = *(const float4*)(p + 12);
    };

    float acc[4][4][4];
    #pragma unroll
    for (int mt = 0; mt < 4; mt++)
        #pragma unroll
        for (int nt = 0; nt < 4; nt++)
            #pragma unroll
            for (int i = 0; i < 4; i++) acc[mt][nt][i] = 0.f;

    ldg_A(0);
    issue_W(0);
    issue_W(1);

    for (int m = 0; m < NCHUNKS; m++) {
        const int bufA = m & 1;
        const int bufW = m % 3;
        const int kc   = m - (m / 12) * 12;
        const int nc   = m / 12;

        // STS A chunk m (fp32 regs -> fp16 SMEM), 2 x STS.128
        {
            uint4 v0, v1;
            v0.x = pk_h2(aReg[0].x, aReg[0].y);
            v0.y = pk_h2(aReg[0].z, aReg[0].w);
            v0.z = pk_h2(aReg[1].x, aReg[1].y);
            v0.w = pk_h2(aReg[1].z, aReg[1].w);
            v1.x = pk_h2(aReg[2].x, aReg[2].y);
            v1.y = pk_h2(aReg[2].z, aReg[2].w);
            v1.z = pk_h2(aReg[3].x, aReg[3].y);
            v1.w = pk_h2(aReg[3].z, aReg[3].w);
            __half* d = Asm + bufA * A_CH + arow * A_STRH + acol;
            *(uint4*)(d)     = v0;
            *(uint4*)(d + 8) = v1;
        }
        cp_wait<1>();        // W chunk m resident
        __syncthreads();     // A STS visible; previous chunk fully consumed

        if (m + 1 < NCHUNKS) ldg_A(m + 1);
        if (m + 2 < NCHUNKS) issue_W(m + 2);

        // ---- MMA over chunk m: 2 k16-steps x 4 m-tiles x 4 n-tiles ----
        {
            const __half* As = Asm + bufA * A_CH;
            const __half* Ws = Wsm + bufW * W_CH;
            #pragma unroll
            for (int ks = 0; ks < 2; ks++) {
                const int kb = ks * 16;
                unsigned afr[4][4];
                #pragma unroll
                for (int mt = 0; mt < 4; mt++) {
                    const int r0 = m_off + mt * 16 + group;
                    const __half* ap = As + r0 * A_STRH + kb + 2 * t4;
                    afr[mt][0] = *(const unsigned*)(ap);
                    afr[mt][1] = *(const unsigned*)(ap + 8 * A_STRH);
                    afr[mt][2] = *(const unsigned*)(ap + 8);
                    afr[mt][3] = *(const unsigned*)(ap + 8 * A_STRH + 8);
                }
                unsigned bfr[4][2];
                #pragma unroll
                for (int nt = 0; nt < 4; nt++) {
                    const __half* bp = Ws + (n_off + nt * 8 + group) * W_STRH + kb + 2 * t4;
                    bfr[nt][0] = *(const unsigned*)(bp);
                    bfr[nt][1] = *(const unsigned*)(bp + 8);
                }
                #pragma unroll
                for (int mt = 0; mt < 4; mt++)
                    #pragma unroll
                    for (int nt = 0; nt < 4; nt++)
                        mma_f16(acc[mt][nt], afr[mt], bfr[nt]);
            }
        }

        // ---- epilogue at end of each n-chunk: gelu + dot with z[eb] ----
        if (kc == 11) {
            #pragma unroll
            for (int mt = 0; mt < 4; mt++) {
                const int r0  = m_off + mt * 16 + group;
                const int ebA = eb_s[r0];
                const int ebB = eb_s[r0 + 8];
                float pA = 0.f, pB = 0.f;
                #pragma unroll
                for (int nt = 0; nt < 4; nt++) {
                    const int c0 = nc * 128 + n_off + nt * 8 + 2 * t4;
                    const float bb0 = b1s[c0], bb1 = b1s[c0 + 1];
                    const float2 zA = *(const float2*)(g_z + (long)ebA * ADIM + c0);
                    const float2 zB = *(const float2*)(g_z + (long)ebB * ADIM + c0);
                    pA += gelu_exact(acc[mt][nt][0] + bb0) * zA.x
                        + gelu_exact(acc[mt][nt][1] + bb1) * zA.y;
                    pB += gelu_exact(acc[mt][nt][2] + bb0) * zB.x
                        + gelu_exact(acc[mt][nt][3] + bb1) * zB.y;
                    acc[mt][nt][0] = 0.f; acc[mt][nt][1] = 0.f;
                    acc[mt][nt][2] = 0.f; acc[mt][nt][3] = 0.f;
                }
                pA += __shfl_xor_sync(0xffffffffu, pA, 1);
                pA += __shfl_xor_sync(0xffffffffu, pA, 2);
                pB += __shfl_xor_sync(0xffffffffu, pB, 1);
                pB += __shfl_xor_sync(0xffffffffu, pB, 2);
                if (t4 == 0) {
                    atomicAdd(&score_s[r0], pA);
                    atomicAdd(&score_s[r0 + 8], pB);
                }
            }
        }
    }

    __syncthreads();
    if (tid < MT) out[e0 + tid] = score_s[tid] + g_cb[eb_s[tid]];
}

// ---------------------------------------------------------------------------
extern "C" void kernel_launch(void* const* d_in, const int* in_sizes, int n_in,
                              void* d_out, int out_size) {
    const float* hidden = (const float*)d_in[0];
    const float* rel    = (const float*)d_in[1];
    const float* nod    = (const float*)d_in[2];
    const float* hed    = (const float*)d_in[3];
    const int*   eb     = (const int*)d_in[4];
    // d_in[5] = edge_ptr : unused by the reference
    const float* Wq     = (const float*)d_in[6];
    const float* Wr     = (const float*)d_in[7];
    const float* Wn     = (const float*)d_in[8];
    const float* Wh     = (const float*)d_in[9];
    const float* W1     = (const float*)d_in[10];
    const float* b1     = (const float*)d_in[11];
    const float* W2     = (const float*)d_in[12];
    const float* b2     = (const float*)d_in[13];
    float* out = (float*)d_out;

    const int E = in_sizes[4];          // 262144 = 2048 * 128
    const int nblocks = E / MT;

    query_kernel<<<BTOT, ADIM>>>(hidden, Wq);
    z_kernel<<<ADIM, 128>>>(W2);
    cb_kernel<<<BTOT, ADIM>>>(b2);
    c_kernel<<<ADIM, ADIM>>>(Wr, Wn, Wh, W1);

    cudaFuncSetAttribute(fused_kernel, cudaFuncAttributeMaxDynamicSharedMemorySize,
                         SMEM_BYTES);
    fused_kernel<<<nblocks, NTHREADS, SMEM_BYTES>>>(rel, nod, hed, eb, b1, out);
}

// round 8
// speedup vs baseline: 1.1327x; 1.1327x over previous
#include <cuda_runtime.h>
#include <cuda_fp16.h>
#include <cstdint>
#include <math.h>

// Problem constants
#define BTOT 128
#define HDIM 128
#define ADIM 384
#define MT   64             // edges per CTA tile (R6 operating point)
#define NTHREADS 256        // 8 warps
#define NCHUNKS 36          // 3 n-chunks x 12 k-chunks (k=32 each)

#define A_STRH 40           // A chunk [64][32] halves, padded stride (ldmatrix conflict-free)
#define W_STRH 40           // W chunk [128 n][32 k] halves, padded stride
#define A_CH (MT * A_STRH)       // 2560 halves per buffer
#define W_CH (128 * W_STRH)      // 5120 halves per buffer

// SMEM bytes: A 2 bufs + W 3 bufs + b1 + score + eb = 43008 B -> 3 CTAs/SM
#define SMEM_BYTES (2 * A_CH * 2 + 3 * W_CH * 2 + ADIM * 4 + MT * 4 + MT * 4)

// device scratch (no cudaMalloc allowed)
__device__ float g_query[BTOT * ADIM];
__device__ float g_qT[ADIM * BTOT];
__device__ float g_z[BTOT * ADIM];
__device__ float g_cb[BTOT];
__device__ __align__(16) __half g_CT[ADIM * ADIM];  // fused weight fp16, [n][k] layout

__device__ __forceinline__ float gelu_exact(float x) {
    return 0.5f * x * (1.0f + erff(x * 0.7071067811865476f));
}

// mma.sync m16n8k16 fp16: D(f32) += A(16x16 f16, row) * B(16x8 f16, col)
__device__ __forceinline__ void mma_f16(float* c, const unsigned* a, const unsigned* b) {
    asm volatile(
        "mma.sync.aligned.m16n8k16.row.col.f32.f16.f16.f32 "
        "{%0,%1,%2,%3}, {%4,%5,%6,%7}, {%8,%9}, {%0,%1,%2,%3};"
        : "+f"(c[0]), "+f"(c[1]), "+f"(c[2]), "+f"(c[3])
        : "r"(a[0]), "r"(a[1]), "r"(a[2]), "r"(a[3]), "r"(b[0]), "r"(b[1]));
}

__device__ __forceinline__ void ldm_x4(unsigned* r, uint32_t addr) {
    asm volatile("ldmatrix.sync.aligned.m8n8.x4.shared.b16 {%0,%1,%2,%3}, [%4];"
                 : "=r"(r[0]), "=r"(r[1]), "=r"(r[2]), "=r"(r[3]) : "r"(addr));
}

__device__ __forceinline__ void cp16(uint32_t smem_dst, const void* gsrc) {
    asm volatile("cp.async.cg.shared.global [%0], [%1], 16;"
                 :: "r"(smem_dst), "l"(__cvta_generic_to_global(gsrc)) : "memory");
}
__device__ __forceinline__ void cp_commit() {
    asm volatile("cp.async.commit_group;" ::: "memory");
}
template <int N>
__device__ __forceinline__ void cp_wait() {
    asm volatile("cp.async.wait_group %0;" :: "n"(N) : "memory");
}
__device__ __forceinline__ uint32_t smem_u32(const void* p) {
    uint32_t a;
    asm("{ .reg .u64 t; cvta.to.shared.u64 t, %1; cvt.u32.u64 %0, t; }" : "=r"(a) : "l"(p));
    return a;
}
__device__ __forceinline__ uint32_t pk_h2(float a, float b) {
    __half2 t = __floats2half2_rn(a, b);   // a -> low half
    return *(uint32_t*)&t;
}

// ---------------------------------------------------------------------------
// Prep kernels (exact fp32 math, validated since R3)
// ---------------------------------------------------------------------------
__global__ void query_kernel(const float* __restrict__ hidden, const float* __restrict__ Wq) {
    __shared__ float hrow[HDIM];
    const int b = blockIdx.x, a = threadIdx.x;
    if (a < HDIM) hrow[a] = hidden[b * HDIM + a];
    __syncthreads();
    float s = 0.f;
    #pragma unroll 8
    for (int h = 0; h < HDIM; h++) s += hrow[h] * Wq[h * ADIM + a];
    g_query[b * ADIM + a] = s;
    g_qT[a * BTOT + b] = s;
}

__global__ void z_kernel(const float* __restrict__ W2) {
    __shared__ float wrow[ADIM];
    const int k = blockIdx.x, b = threadIdx.x;
    for (int i = b; i < ADIM; i += 128) wrow[i] = W2[k * ADIM + i];
    __syncthreads();
    float s = 0.f;
    #pragma unroll 8
    for (int n = 0; n < ADIM; n++) s += wrow[n] * g_qT[n * BTOT + b];
    g_z[b * ADIM + k] = s;
}

__global__ void cb_kernel(const float* __restrict__ b2) {
    __shared__ float red[12];
    const int b = blockIdx.x, t = threadIdx.x;
    float v = b2[t] * g_query[b * ADIM + t];
    #pragma unroll
    for (int o = 16; o > 0; o >>= 1) v += __shfl_down_sync(0xffffffffu, v, o);
    if ((t & 31) == 0) red[t >> 5] = v;
    __syncthreads();
    if (t == 0) {
        float s = 0.f;
        #pragma unroll
        for (int i = 0; i < 12; i++) s += red[i];
        g_cb[b] = s;
    }
}

// C = blockdiag(Wr,Wn,Wh) @ W1, exact fp32, stored fp16 TRANSPOSED [n][k]
__global__ void c_kernel(const float* __restrict__ Wr, const float* __restrict__ Wn,
                         const float* __restrict__ Wh, const float* __restrict__ W1) {
    __shared__ float wrow[HDIM];
    const int kg = blockIdx.x, n = threadIdx.x;
    const int t = kg >> 7, d = kg & 127;
    const float* Wt = (t == 0) ? Wr : ((t == 1) ? Wn : Wh);
    if (n < HDIM) wrow[n] = Wt[d * HDIM + n];
    __syncthreads();
    float s = 0.f;
    #pragma unroll 8
    for (int h = 0; h < HDIM; h++) s += wrow[h] * W1[(t * HDIM + h) * ADIM + n];
    g_CT[n * ADIM + kg] = __float2half_rn(s);
}

// ---------------------------------------------------------------------------
// Main fused kernel: G = X @ C via fp16 m16n8k16 + ldmatrix fragment loads.
// scores = gelu(G+b1).z[eb]+cb[eb]
// 8 warps in 2x4 over [64 x 128]; warp tile 32x32 (2m x 4n). acc 32 regs.
// A: register-lookahead LDG fp32 -> cvt fp16 -> STS (double buffer).
// W: fp16 cp.async 3-stage from transposed g_CT.
// ---------------------------------------------------------------------------
__global__ void __launch_bounds__(NTHREADS, 3)
fused_kernel(const float* __restrict__ rel, const float* __restrict__ nod,
             const float* __restrict__ hed, const int* __restrict__ edge_batch,
             const float* __restrict__ b1, float* __restrict__ out)
{
    extern __shared__ char smem[];
    __half* Asm    = (__half*)smem;                       // 2 * A_CH
    __half* Wsm    = Asm + 2 * A_CH;                      // 3 * W_CH
    float*  b1s    = (float*)(Wsm + 3 * W_CH);
    float*  score_s = b1s + ADIM;
    int*    eb_s   = (int*)(score_s + MT);

    const int tid   = threadIdx.x;
    const int lane  = tid & 31;
    const int warp  = tid >> 5;
    const int group = lane >> 2;
    const int t4    = lane & 3;
    const int m_off = (warp >> 2) * 32;   // 0 or 32
    const int n_off = (warp & 3) * 32;    // 0..96
    const long e0   = (long)blockIdx.x * MT;

    if (tid < MT) {
        eb_s[tid] = edge_batch[e0 + tid];
        score_s[tid] = 0.f;
    }
    for (int i = tid; i < ADIM; i += NTHREADS) b1s[i] = b1[i];

    const uint32_t sA = smem_u32(Asm);
    const uint32_t sW = smem_u32(Wsm);

    // ldmatrix lane-derived offsets (halves)
    const int a_lrow = lane & 15;              // row within 16-row m-tile
    const int a_lcol = (lane >> 4) * 8;        // k sub-block 0 / 8
    const int b_mat  = lane >> 3;              // 0..3
    const int b_lrow = (b_mat >> 1) * 8 + (lane & 7);   // n row within 16-n pair
    const int b_lcol = (b_mat & 1) * 8;        // k sub-block 0 / 8

    // W chunk m -> buffer m%3 : 128 n-rows x 32 k halves, 2 cp16/thread
    auto issue_W = [&](int m) {
        const int nc = m / 12;
        const int k0 = (m - nc * 12) * 32;
        const uint32_t base = sW + (m % 3) * (W_CH * 2);
        #pragma unroll
        for (int j = 0; j < 2; j++) {
            const int idx = tid + NTHREADS * j;
            const int n = idx >> 2, c = idx & 3;
            cp16(base + (n * W_STRH + c * 8) * 2,
                 g_CT + (long)(nc * 128 + n) * ADIM + k0 + c * 8);
        }
        cp_commit();
    };

    // A chunk lookahead: 8 floats/thread (row r = tid>>2, seg s = tid&3)
    const int arow = tid >> 2, aseg = tid & 3;
    float4 aReg[2];
    auto ldg_A = [&](int m) {
        const int nc = m / 12;
        const int k0 = (m - nc * 12) * 32;
        const int tt = k0 >> 7, col0 = k0 & 127;
        const float* src = (tt == 0) ? rel : ((tt == 1) ? nod : hed);
        const float* p = src + (e0 + arow) * HDIM + col0 + aseg * 8;
        aReg[0] = *(const float4*)(p);
        aReg[1] = *(const float4*)(p + 4);
    };

    float acc[2][4][4];
    #pragma unroll
    for (int mt = 0; mt < 2; mt++)
        #pragma unroll
        for (int nt = 0; nt < 4; nt++)
            #pragma unroll
            for (int i = 0; i < 4; i++) acc[mt][nt][i] = 0.f;

    ldg_A(0);
    issue_W(0);
    issue_W(1);

    for (int m = 0; m < NCHUNKS; m++) {
        const int bufA = m & 1;
        const int bufW = m % 3;
        const int kc   = m - (m / 12) * 12;
        const int nc   = m / 12;

        // STS A chunk m (fp32 regs -> fp16 SMEM)
        {
            uint4 v;
            v.x = pk_h2(aReg[0].x, aReg[0].y);
            v.y = pk_h2(aReg[0].z, aReg[0].w);
            v.z = pk_h2(aReg[1].x, aReg[1].y);
            v.w = pk_h2(aReg[1].z, aReg[1].w);
            *(uint4*)(Asm + bufA * A_CH + arow * A_STRH + aseg * 8) = v;
        }
        cp_wait<1>();        // W chunk m resident
        __syncthreads();     // A STS visible; previous chunk fully consumed

        if (m + 1 < NCHUNKS) ldg_A(m + 1);
        if (m + 2 < NCHUNKS) issue_W(m + 2);

        // ---- MMA over chunk m: 2 k16-steps, ldmatrix fragment loads ----
        {
            const uint32_t aBase = sA + bufA * (A_CH * 2);
            const uint32_t wBase = sW + bufW * (W_CH * 2);
            #pragma unroll
            for (int ks = 0; ks < 2; ks++) {
                const int kb = ks * 16;
                unsigned afr[2][4];
                #pragma unroll
                for (int mt = 0; mt < 2; mt++)
                    ldm_x4(afr[mt], aBase +
                           ((m_off + mt * 16 + a_lrow) * A_STRH + kb + a_lcol) * 2);
                unsigned bfr[4][2];
                #pragma unroll
                for (int p = 0; p < 2; p++) {
                    unsigned bq[4];
                    ldm_x4(bq, wBase +
                           ((n_off + p * 16 + b_lrow) * W_STRH + kb + b_lcol) * 2);
                    bfr[2 * p][0]     = bq[0];
                    bfr[2 * p][1]     = bq[1];
                    bfr[2 * p + 1][0] = bq[2];
                    bfr[2 * p + 1][1] = bq[3];
                }
                #pragma unroll
                for (int mt = 0; mt < 2; mt++)
                    #pragma unroll
                    for (int nt = 0; nt < 4; nt++)
                        mma_f16(acc[mt][nt], afr[mt], bfr[nt]);
            }
        }

        // ---- epilogue at end of each n-chunk: gelu + dot with z[eb] ----
        if (kc == 11) {
            #pragma unroll
            for (int mt = 0; mt < 2; mt++) {
                const int r0  = m_off + mt * 16 + group;
                const int ebA = eb_s[r0];
                const int ebB = eb_s[r0 + 8];
                float pA = 0.f, pB = 0.f;
                #pragma unroll
                for (int nt = 0; nt < 4; nt++) {
                    const int c0 = nc * 128 + n_off + nt * 8 + 2 * t4;
                    const float bb0 = b1s[c0], bb1 = b1s[c0 + 1];
                    const float2 zA = *(const float2*)(g_z + (long)ebA * ADIM + c0);
                    const float2 zB = *(const float2*)(g_z + (long)ebB * ADIM + c0);
                    pA += gelu_exact(acc[mt][nt][0] + bb0) * zA.x
                        + gelu_exact(acc[mt][nt][1] + bb1) * zA.y;
                    pB += gelu_exact(acc[mt][nt][2] + bb0) * zB.x
                        + gelu_exact(acc[mt][nt][3] + bb1) * zB.y;
                    acc[mt][nt][0] = 0.f; acc[mt][nt][1] = 0.f;
                    acc[mt][nt][2] = 0.f; acc[mt][nt][3] = 0.f;
                }
                pA += __shfl_xor_sync(0xffffffffu, pA, 1);
                pA += __shfl_xor_sync(0xffffffffu, pA, 2);
                pB += __shfl_xor_sync(0xffffffffu, pB, 1);
                pB += __shfl_xor_sync(0xffffffffu, pB, 2);
                if (t4 == 0) {
                    atomicAdd(&score_s[r0], pA);
                    atomicAdd(&score_s[r0 + 8], pB);
                }
            }
        }
    }

    __syncthreads();
    if (tid < MT) out[e0 + tid] = score_s[tid] + g_cb[eb_s[tid]];
}

// ---------------------------------------------------------------------------
extern "C" void kernel_launch(void* const* d_in, const int* in_sizes, int n_in,
                              void* d_out, int out_size) {
    const float* hidden = (const float*)d_in[0];
    const float* rel    = (const float*)d_in[1];
    const float* nod    = (const float*)d_in[2];
    const float* hed    = (const float*)d_in[3];
    const int*   eb     = (const int*)d_in[4];
    // d_in[5] = edge_ptr : unused by the reference
    const float* Wq     = (const float*)d_in[6];
    const float* Wr     = (const float*)d_in[7];
    const float* Wn     = (const float*)d_in[8];
    const float* Wh     = (const float*)d_in[9];
    const float* W1     = (const float*)d_in[10];
    const float* b1     = (const float*)d_in[11];
    const float* W2     = (const float*)d_in[12];
    const float* b2     = (const float*)d_in[13];
    float* out = (float*)d_out;

    const int E = in_sizes[4];          // 262144 = 4096 * 64
    const int nblocks = E / MT;

    query_kernel<<<BTOT, ADIM>>>(hidden, Wq);
    z_kernel<<<ADIM, 128>>>(W2);
    cb_kernel<<<BTOT, ADIM>>>(b2);
    c_kernel<<<ADIM, ADIM>>>(Wr, Wn, Wh, W1);

    cudaFuncSetAttribute(fused_kernel, cudaFuncAttributeMaxDynamicSharedMemorySize,
                         SMEM_BYTES);
    fused_kernel<<<nblocks, NTHREADS, SMEM_BYTES>>>(rel, nod, hed, eb, b1, out);
}